// round 1
// baseline (speedup 1.0000x reference)
#include <cuda_runtime.h>
#include <cuda_bf16.h>

// Problem dims
#define Bn   8
#define Nn   6
#define Dn   41
#define FHn  8
#define FWn  22
#define Cn   64
#define NX0  200
#define NX1  200

constexpr int NPRIME      = Bn * Nn * Dn * FHn * FWn;     // 346368
constexpr int PTS_PER_B   = Nn * Dn * FHn * FWn;          // 43296
constexpr int PTS_PER_N   = Dn * FHn * FWn;               // 7216
constexpr int PTS_PER_D   = FHn * FWn;                    // 176
constexpr int VOX_PER_B   = NX0 * NX1;                    // 40000
constexpr int GRID_FLOATS = Bn * VOX_PER_B * Cn;          // 20,480,000 (81.92 MB)

// Scratch: [b*40000 + gx*200 + gy][C]  (channel-contiguous for float4 atomics)
__device__ float g_scratch[GRID_FLOATS];
// Per-camera transform pack: M1[9], t1[3], M2[9], trans[3] = 24 floats x 48 cams
__device__ float g_mats[48 * 24];

// ---------------------------------------------------------------------------
// 3x3 inverse via adjugate
__device__ __forceinline__ void inv3(const float* m, float* o) {
    float a = m[0], b = m[1], c = m[2];
    float d = m[3], e = m[4], f = m[5];
    float g = m[6], h = m[7], i = m[8];
    float A  = e * i - f * h;
    float Bc = -(d * i - f * g);
    float Cc = d * h - e * g;
    float det = a * A + b * Bc + c * Cc;
    float inv = 1.0f / det;
    o[0] = A * inv;            o[1] = (c * h - b * i) * inv; o[2] = (b * f - c * e) * inv;
    o[3] = Bc * inv;           o[4] = (a * i - c * g) * inv; o[5] = (c * d - a * f) * inv;
    o[6] = Cc * inv;           o[7] = (b * g - a * h) * inv; o[8] = (a * e - b * d) * inv;
}

__global__ void precompute_kernel(const float* __restrict__ rots,
                                  const float* __restrict__ trans,
                                  const float* __restrict__ intrins,
                                  const float* __restrict__ post_rots,
                                  const float* __restrict__ post_trans) {
    int cam = threadIdx.x;
    if (cam >= Bn * Nn) return;
    float M1[9], Ki[9], M2[9];
    inv3(post_rots + cam * 9, M1);
    inv3(intrins + cam * 9, Ki);
    const float* R = rots + cam * 9;
    #pragma unroll
    for (int i = 0; i < 3; i++)
        #pragma unroll
        for (int j = 0; j < 3; j++)
            M2[i * 3 + j] = R[i * 3 + 0] * Ki[0 + j] + R[i * 3 + 1] * Ki[3 + j] + R[i * 3 + 2] * Ki[6 + j];
    const float* pt = post_trans + cam * 3;
    float t1[3];
    #pragma unroll
    for (int i = 0; i < 3; i++)
        t1[i] = M1[i * 3 + 0] * pt[0] + M1[i * 3 + 1] * pt[1] + M1[i * 3 + 2] * pt[2];

    float* o = g_mats + cam * 24;
    #pragma unroll
    for (int i = 0; i < 9; i++) o[i] = M1[i];
    #pragma unroll
    for (int i = 0; i < 3; i++) o[9 + i] = t1[i];
    #pragma unroll
    for (int i = 0; i < 9; i++) o[12 + i] = M2[i];
    const float* tr = trans + cam * 3;
    #pragma unroll
    for (int i = 0; i < 3; i++) o[21 + i] = tr[i];
}

// ---------------------------------------------------------------------------
__global__ void zero_kernel() {
    int i = blockIdx.x * blockDim.x + threadIdx.x;
    if (i < GRID_FLOATS / 4) {
        float4 z = make_float4(0.f, 0.f, 0.f, 0.f);
        reinterpret_cast<float4*>(g_scratch)[i] = z;
    }
}

// ---------------------------------------------------------------------------
// One thread per (point, channel-quad): 16 threads per point.
// Geometry is recomputed redundantly per lane-group (cheap ALU); feature loads
// and float4 atomics are fully coalesced across the 16 lanes of a point.
__global__ void scatter_kernel(const float4* __restrict__ feats) {
    int gid = blockIdx.x * blockDim.x + threadIdx.x;   // < NPRIME * 16
    int p = gid >> 4;
    int q = gid & 15;

    int b  = p / PTS_PER_B;
    int r  = p - b * PTS_PER_B;
    int n  = r / PTS_PER_N;
    int r2 = r - n * PTS_PER_N;
    int d  = r2 / PTS_PER_D;
    int r3 = r2 - d * PTS_PER_D;
    int h  = r3 / FWn;
    int w  = r3 - h * FWn;

    const float* M = g_mats + (b * Nn + n) * 24;

    // frustum coords: xs = linspace(0, 351, 22)[w], ys = linspace(0, 127, 8)[h], ds = 4 + d
    float fx = (float)w * (351.0f / 21.0f);
    float fy = (float)h * (127.0f / 7.0f);
    float fd = 4.0f + (float)d;

    // pt = inv(post_rots) @ (f - post_trans)  ==  M1 @ f - t1
    float px = M[0] * fx + M[1] * fy + M[2] * fd - M[9];
    float py = M[3] * fx + M[4] * fy + M[5] * fd - M[10];
    float pz = M[6] * fx + M[7] * fy + M[8] * fd - M[11];

    // unproject: (u*d, v*d, d)
    float x2 = px * pz;
    float y2 = py * pz;
    float z2 = pz;

    // geom = (rots @ inv(intrins)) @ pt2 + trans
    float gxw = M[12] * x2 + M[13] * y2 + M[14] * z2 + M[21];
    float gyw = M[15] * x2 + M[16] * y2 + M[17] * z2 + M[22];
    float gzw = M[18] * x2 + M[19] * y2 + M[20] * z2 + M[23];

    // voxelize: (geom - (BX - DX/2)) / DX, truncate toward zero (matches astype(int32))
    int gx = (int)((gxw + 50.0f) / 0.5f);
    int gy = (int)((gyw + 50.0f) / 0.5f);
    int gz = (int)((gzw + 10.0f) / 20.0f);

    if (gx < 0 || gx >= NX0 || gy < 0 || gy >= NX1 || gz != 0) return;

    int voxel = (b * NX0 + gx) * NX1 + gy;
    float4 v = feats[p * 16 + q];
    atomicAdd(reinterpret_cast<float4*>(g_scratch) + voxel * 16 + q, v);
}

// ---------------------------------------------------------------------------
// Transpose scratch [b][pos][c] -> out [b][c][pos], tiles of 64 positions.
// smem tile padded to stride 65 -> conflict-free both phases; global accesses
// coalesced both phases.
__global__ void transpose_kernel(float* __restrict__ out) {
    __shared__ float tile[64][65];
    int blk  = blockIdx.x;                 // 8 * 625 = 5000 blocks
    int b    = blk / (VOX_PER_B / 64);
    int pos0 = (blk - b * (VOX_PER_B / 64)) * 64;
    int t    = threadIdx.x;                // 256

    const float* src = g_scratch + (size_t)(b * VOX_PER_B + pos0) * Cn;
    #pragma unroll
    for (int j = 0; j < 16; j++) {
        int idx = t + 256 * j;             // 0..4095
        int pos = idx >> 6;
        int c   = idx & 63;
        tile[pos][c] = src[idx];
    }
    __syncthreads();

    float* dst = out + (size_t)b * Cn * VOX_PER_B + pos0;
    #pragma unroll
    for (int j = 0; j < 16; j++) {
        int idx = t + 256 * j;
        int c   = idx >> 6;
        int pos = idx & 63;
        dst[c * VOX_PER_B + pos] = tile[pos][c];
    }
}

// ---------------------------------------------------------------------------
extern "C" void kernel_launch(void* const* d_in, const int* in_sizes, int n_in,
                              void* d_out, int out_size) {
    const float* x_feats    = (const float*)d_in[0];
    const float* rots       = (const float*)d_in[1];
    const float* trans      = (const float*)d_in[2];
    const float* intrins    = (const float*)d_in[3];
    const float* post_rots  = (const float*)d_in[4];
    const float* post_trans = (const float*)d_in[5];
    float* out = (float*)d_out;

    // 1. zero scratch grid
    zero_kernel<<<(GRID_FLOATS / 4 + 255) / 256, 256>>>();
    // 2. per-camera matrix precompute
    precompute_kernel<<<1, 64>>>(rots, trans, intrins, post_rots, post_trans);
    // 3. scatter features with float4 atomics
    scatter_kernel<<<(NPRIME * 16) / 256, 256>>>(
        reinterpret_cast<const float4*>(x_feats));
    // 4. transpose to output layout [B, C, 200, 200]
    transpose_kernel<<<Bn * (VOX_PER_B / 64), 256>>>(out);
}

// round 3
// speedup vs baseline: 1.1915x; 1.1915x over previous
#include <cuda_runtime.h>
#include <cuda_bf16.h>

// Problem dims
#define Bn   8
#define Nn   6
#define Dn   41
#define FHn  8
#define FWn  22
#define Cn   64
#define NX0  200
#define NX1  200

constexpr int NPRIME      = Bn * Nn * Dn * FHn * FWn;     // 346368
constexpr int PTS_PER_B   = Nn * Dn * FHn * FWn;          // 43296
constexpr int PTS_PER_N   = Dn * FHn * FWn;               // 7216
constexpr int PTS_PER_D   = FHn * FWn;                    // 176
constexpr int VOX_PER_B   = NX0 * NX1;                    // 40000
constexpr int GRID_FLOATS = Bn * VOX_PER_B * Cn;          // 20,480,000 (81.92 MB)
constexpr int TILES_PER_B = VOX_PER_B / 64;               // 625
constexpr int NTILES      = Bn * TILES_PER_B;             // 5000

// Scratch: [b*40000 + gx*200 + gy][C]  (channel-contiguous for float4 atomics)
// Self-contained per call: zero_kernel clears scratch AND flags at the START
// of every kernel_launch; no state carried between calls.
__device__ __align__(16) float g_scratch[GRID_FLOATS];
__device__ unsigned int g_touched[NTILES];   // 0/1 per 64-voxel tile
// Per-camera transform pack: M1[9], t1[3], M2[9], trans[3] = 24 floats x 48 cams
__device__ float g_mats[48 * 24];

// ---------------------------------------------------------------------------
__device__ __forceinline__ void inv3(const float* m, float* o) {
    float a = m[0], b = m[1], c = m[2];
    float d = m[3], e = m[4], f = m[5];
    float g = m[6], h = m[7], i = m[8];
    float A  = e * i - f * h;
    float Bc = -(d * i - f * g);
    float Cc = d * h - e * g;
    float det = a * A + b * Bc + c * Cc;
    float inv = 1.0f / det;
    o[0] = A * inv;            o[1] = (c * h - b * i) * inv; o[2] = (b * f - c * e) * inv;
    o[3] = Bc * inv;           o[4] = (a * i - c * g) * inv; o[5] = (c * d - a * f) * inv;
    o[6] = Cc * inv;           o[7] = (b * g - a * h) * inv; o[8] = (a * e - b * d) * inv;
}

__global__ void precompute_kernel(const float* __restrict__ rots,
                                  const float* __restrict__ trans,
                                  const float* __restrict__ intrins,
                                  const float* __restrict__ post_rots,
                                  const float* __restrict__ post_trans) {
    int cam = threadIdx.x;
    if (cam >= Bn * Nn) return;
    float M1[9], Ki[9], M2[9];
    inv3(post_rots + cam * 9, M1);
    inv3(intrins + cam * 9, Ki);
    const float* R = rots + cam * 9;
    #pragma unroll
    for (int i = 0; i < 3; i++)
        #pragma unroll
        for (int j = 0; j < 3; j++)
            M2[i * 3 + j] = R[i * 3 + 0] * Ki[0 + j] + R[i * 3 + 1] * Ki[3 + j] + R[i * 3 + 2] * Ki[6 + j];
    const float* pt = post_trans + cam * 3;
    float t1[3];
    #pragma unroll
    for (int i = 0; i < 3; i++)
        t1[i] = M1[i * 3 + 0] * pt[0] + M1[i * 3 + 1] * pt[1] + M1[i * 3 + 2] * pt[2];

    float* o = g_mats + cam * 24;
    #pragma unroll
    for (int i = 0; i < 9; i++) o[i] = M1[i];
    #pragma unroll
    for (int i = 0; i < 3; i++) o[9 + i] = t1[i];
    #pragma unroll
    for (int i = 0; i < 9; i++) o[12 + i] = M2[i];
    const float* tr = trans + cam * 3;
    #pragma unroll
    for (int i = 0; i < 3; i++) o[21 + i] = tr[i];
}

// ---------------------------------------------------------------------------
// Zero scratch (float4) and touched flags. Runs first -> call is self-contained.
__global__ void zero_kernel() {
    int i = blockIdx.x * blockDim.x + threadIdx.x;
    if (i < GRID_FLOATS / 4) {
        float4 z = make_float4(0.f, 0.f, 0.f, 0.f);
        reinterpret_cast<float4*>(g_scratch)[i] = z;
    }
    if (i < NTILES) g_touched[i] = 0;
}

// ---------------------------------------------------------------------------
// One thread per (point, channel-quad): 16 threads per point.
__global__ void scatter_kernel(const float4* __restrict__ feats) {
    int gid = blockIdx.x * blockDim.x + threadIdx.x;   // < NPRIME * 16
    int p = gid >> 4;
    int q = gid & 15;

    int b  = p / PTS_PER_B;
    int r  = p - b * PTS_PER_B;
    int n  = r / PTS_PER_N;
    int r2 = r - n * PTS_PER_N;
    int d  = r2 / PTS_PER_D;
    int r3 = r2 - d * PTS_PER_D;
    int h  = r3 / FWn;
    int w  = r3 - h * FWn;

    const float* M = g_mats + (b * Nn + n) * 24;

    float fx = (float)w * (351.0f / 21.0f);
    float fy = (float)h * (127.0f / 7.0f);
    float fd = 4.0f + (float)d;

    // pt = inv(post_rots) @ (f - post_trans)  ==  M1 @ f - t1
    float px = M[0] * fx + M[1] * fy + M[2] * fd - M[9];
    float py = M[3] * fx + M[4] * fy + M[5] * fd - M[10];
    float pz = M[6] * fx + M[7] * fy + M[8] * fd - M[11];

    // unproject: (u*d, v*d, d)
    float x2 = px * pz;
    float y2 = py * pz;
    float z2 = pz;

    // geom = (rots @ inv(intrins)) @ pt2 + trans
    float gxw = M[12] * x2 + M[13] * y2 + M[14] * z2 + M[21];
    float gyw = M[15] * x2 + M[16] * y2 + M[17] * z2 + M[22];
    float gzw = M[18] * x2 + M[19] * y2 + M[20] * z2 + M[23];

    // voxelize (truncate toward zero matches astype(int32))
    int gx = (int)((gxw + 50.0f) / 0.5f);
    int gy = (int)((gyw + 50.0f) / 0.5f);
    int gz = (int)((gzw + 10.0f) / 20.0f);

    if (gx < 0 || gx >= NX0 || gy < 0 || gy >= NX1 || gz != 0) return;

    int vox   = gx * NX1 + gy;                 // within batch
    int voxel = b * VOX_PER_B + vox;           // global
    if (q == 0) g_touched[b * TILES_PER_B + (vox >> 6)] = 1;  // idempotent

    // streaming read: feature data is touched exactly once
    float4 v = __ldcs(&feats[p * 16 + q]);
    atomicAdd(reinterpret_cast<float4*>(g_scratch) + voxel * 16 + q, v);
}

// ---------------------------------------------------------------------------
// Finalize: per 64-voxel tile. Untouched -> write zeros to out (skip scratch
// read). Touched -> read scratch (float4), transpose via smem, write out.
// Leaves scratch/flags dirty; next call's zero_kernel handles cleanup.
__global__ void finalize_kernel(float* __restrict__ out) {
    __shared__ float tile[64][65];
    int blk  = blockIdx.x;                 // NTILES = 5000
    int b    = blk / TILES_PER_B;
    int tIdx = blk - b * TILES_PER_B;
    int pos0 = tIdx * 64;
    int t    = threadIdx.x;                // 256

    float* dst = out + (size_t)b * Cn * VOX_PER_B + pos0;

    if (g_touched[blk] == 0) {
        float4 z = make_float4(0.f, 0.f, 0.f, 0.f);
        #pragma unroll
        for (int k = 0; k < 4; k++) {
            int i = t + 256 * k;           // 0..1023 float4 slots
            int c = i >> 4;
            int p = (i & 15) * 4;
            __stcs(reinterpret_cast<float4*>(dst + (size_t)c * VOX_PER_B + p), z);
        }
        return;
    }

    const float4* src4 = reinterpret_cast<const float4*>(
        g_scratch + (size_t)(b * VOX_PER_B + pos0) * Cn);   // 1024 float4
    #pragma unroll
    for (int k = 0; k < 4; k++) {
        int i = t + 256 * k;
        float4 v = src4[i];
        int pos = i >> 4;
        int c4  = (i & 15) * 4;
        tile[pos][c4 + 0] = v.x;
        tile[pos][c4 + 1] = v.y;
        tile[pos][c4 + 2] = v.z;
        tile[pos][c4 + 3] = v.w;
    }
    __syncthreads();

    #pragma unroll
    for (int k = 0; k < 4; k++) {
        int i = t + 256 * k;
        int c = i >> 4;
        int p = (i & 15) * 4;
        float4 v = make_float4(tile[p + 0][c], tile[p + 1][c],
                               tile[p + 2][c], tile[p + 3][c]);
        __stcs(reinterpret_cast<float4*>(dst + (size_t)c * VOX_PER_B + p), v);
    }
}

// ---------------------------------------------------------------------------
extern "C" void kernel_launch(void* const* d_in, const int* in_sizes, int n_in,
                              void* d_out, int out_size) {
    const float* x_feats    = (const float*)d_in[0];
    const float* rots       = (const float*)d_in[1];
    const float* trans      = (const float*)d_in[2];
    const float* intrins    = (const float*)d_in[3];
    const float* post_rots  = (const float*)d_in[4];
    const float* post_trans = (const float*)d_in[5];
    float* out = (float*)d_out;

    // 1. zero scratch + flags (self-contained call)
    zero_kernel<<<(GRID_FLOATS / 4 + 255) / 256, 256>>>();
    // 2. per-camera matrix precompute
    precompute_kernel<<<1, 64>>>(rots, trans, intrins, post_rots, post_trans);
    // 3. scatter features with float4 atomics
    scatter_kernel<<<(NPRIME * 16) / 256, 256>>>(
        reinterpret_cast<const float4*>(x_feats));
    // 4. transpose touched tiles to output layout [B, C, 200, 200]
    finalize_kernel<<<NTILES, 256>>>(out);
}